// round 2
// baseline (speedup 1.0000x reference)
#include <cuda_runtime.h>
#include <math.h>

#define TOTAL 160
#define NB    16
#define NGR   4
#define DIM   1024
#define CIN   834
#define GF    256
#define SSP   1568   // 8*14*14

// Ragged bookkeeping (static per problem spec: COUNTS are compile-time constants)
__constant__ int c_off[NB + 1] = {0, 6, 20, 30, 38, 54, 66, 75, 86, 93,
                                  106, 116, 126, 134, 146, 152, 160};

// Scratch (device globals — no runtime allocation)
__device__ float g_emb[TOTAL * NGR * GF];    // [t][g][f]
__device__ float g_q  [TOTAL * NGR * CIN];   // [t][g][c]
__device__ float g_adj[TOTAL * NGR * SSP];   // [t][g][s]  logits -> softmax in place
__device__ float g_r  [TOTAL * NGR * CIN];   // [t][g][c]
__device__ float g_upd[TOTAL * NGR * GF];    // [t][g][f]

// ---------------------------------------------------------------------------
// Generic 64x64 block tiled fp32 GEMM core. C[M,N] = A[M,K] * op(B) (+epilogue)
// A is row-major [M,K] (lda). TB=false: B row-major [K,N]; TB=true: B row-major [N,K].
// 256 threads, 4x4 micro-tile per thread, K-tile 16.
// ---------------------------------------------------------------------------
template<bool TB, bool RELU, bool BIAS, bool ADDEND>
__device__ __forceinline__ void gemm_tile_core(
    const float* __restrict__ A, int lda,
    const float* __restrict__ B, int ldb,
    float* __restrict__ C, int ldc,
    int M, int N, int K,
    const float* __restrict__ bias,           // per-column bias [N]
    const float* __restrict__ add, int ldadd) // addend matrix same shape as C
{
    __shared__ float As[16][65];
    __shared__ float Bs[16][65];

    const int tid = threadIdx.x;
    const int tx  = tid & 15;
    const int ty  = tid >> 4;
    const int m0  = blockIdx.y * 64;
    const int n0  = blockIdx.x * 64;

    const int ra  = tid >> 2;         // 0..63
    const int ka4 = (tid & 3) * 4;    // 0,4,8,12

    float acc[4][4];
#pragma unroll
    for (int i = 0; i < 4; i++)
#pragma unroll
        for (int j = 0; j < 4; j++) acc[i][j] = 0.f;

    for (int kt = 0; kt < K; kt += 16) {
        // --- load A tile -> As[k][m]
        {
            const int m = m0 + ra;
#pragma unroll
            for (int j = 0; j < 4; j++) {
                const int k = kt + ka4 + j;
                float v = 0.f;
                if (m < M && k < K) v = A[(long)m * lda + k];
                As[ka4 + j][ra] = v;
            }
        }
        // --- load B tile -> Bs[k][n]
        if (TB) {
            const int n = n0 + ra;
#pragma unroll
            for (int j = 0; j < 4; j++) {
                const int k = kt + ka4 + j;
                float v = 0.f;
                if (n < N && k < K) v = B[(long)n * ldb + k];
                Bs[ka4 + j][ra] = v;
            }
        } else {
            const int kk = tid >> 4;          // 0..15
            const int nn = (tid & 15) * 4;    // 0..60
            const int k  = kt + kk;
#pragma unroll
            for (int j = 0; j < 4; j++) {
                const int n = n0 + nn + j;
                float v = 0.f;
                if (k < K && n < N) v = B[(long)k * ldb + n];
                Bs[kk][nn + j] = v;
            }
        }
        __syncthreads();

#pragma unroll
        for (int k = 0; k < 16; k++) {
            float a[4], b[4];
#pragma unroll
            for (int i = 0; i < 4; i++) a[i] = As[k][ty * 4 + i];
#pragma unroll
            for (int j = 0; j < 4; j++) b[j] = Bs[k][tx * 4 + j];
#pragma unroll
            for (int i = 0; i < 4; i++)
#pragma unroll
                for (int j = 0; j < 4; j++)
                    acc[i][j] += a[i] * b[j];
        }
        __syncthreads();
    }

    // --- epilogue
#pragma unroll
    for (int i = 0; i < 4; i++) {
        const int m = m0 + ty * 4 + i;
        if (m >= M) continue;
#pragma unroll
        for (int j = 0; j < 4; j++) {
            const int n = n0 + tx * 4 + j;
            if (n >= N) continue;
            float v = acc[i][j];
            if (BIAS)   v += bias[n];
            if (ADDEND) v += add[(long)m * ldadd + n];
            if (RELU)   v = fmaxf(v, 0.f);
            C[(long)m * ldc + n] = v;
        }
    }
}

// ---------------------------------------------------------------------------
// Stage kernels
// ---------------------------------------------------------------------------

// emb[t, g*256+f] = actor @ W_a^T + b_a       [160,1024]x[1024,1024]^T
__global__ void k_emb(const float* __restrict__ A, const float* __restrict__ Wa,
                      const float* __restrict__ ba) {
    gemm_tile_core<true, false, true, false>(
        A, DIM, Wa, DIM, g_emb, NGR * GF,
        TOTAL, NGR * GF, DIM, ba, nullptr, 0);
}

// q[t,g,c] = emb[t,g,:] @ W_c[g]              per g: [160,256]x[256,834]
__global__ void k_q(const float* __restrict__ Wc) {
    const int g = blockIdx.z;
    gemm_tile_core<false, false, false, false>(
        g_emb + g * GF, NGR * GF,
        Wc + (long)g * GF * CIN, CIN,
        g_q + g * CIN, NGR * CIN,
        TOTAL, CIN, GF, nullptr, nullptr, 0);
}

// logits[t,g,s] = q[t,g,:] @ fm[b]            per b: [4*cnt,834]x[834,1568]
__global__ void k_logits(const float* __restrict__ fm) {
    const int b = blockIdx.z;
    const int off = c_off[b];
    const int cnt = c_off[b + 1] - off;
    gemm_tile_core<false, false, false, false>(
        g_q + (long)off * NGR * CIN, CIN,
        fm + (long)b * CIN * SSP, SSP,
        g_adj + (long)off * NGR * SSP, SSP,
        cnt * NGR, SSP, CIN, nullptr, nullptr, 0);
}

// softmax over s, in place. One block per (t,g) row.
__global__ void k_softmax() {
    const int row = blockIdx.x;
    float* __restrict__ p = g_adj + (long)row * SSP;
    const int t = threadIdx.x;
    __shared__ float sh[8];

    float mx = -1e30f;
    for (int s = t; s < SSP; s += 256) mx = fmaxf(mx, p[s]);
#pragma unroll
    for (int o = 16; o; o >>= 1) mx = fmaxf(mx, __shfl_xor_sync(0xffffffffu, mx, o));
    if ((t & 31) == 0) sh[t >> 5] = mx;
    __syncthreads();
    if (t == 0) {
        float v = sh[0];
        for (int i = 1; i < 8; i++) v = fmaxf(v, sh[i]);
        sh[0] = v;
    }
    __syncthreads();
    mx = sh[0];
    __syncthreads();

    float sum = 0.f;
    for (int s = t; s < SSP; s += 256) {
        const float e = __expf(p[s] - mx);
        p[s] = e;
        sum += e;
    }
#pragma unroll
    for (int o = 16; o; o >>= 1) sum += __shfl_xor_sync(0xffffffffu, sum, o);
    if ((t & 31) == 0) sh[t >> 5] = sum;
    __syncthreads();
    if (t == 0) {
        float v = 0.f;
        for (int i = 0; i < 8; i++) v += sh[i];
        sh[0] = 1.f / v;
    }
    __syncthreads();
    const float inv = sh[0];
    for (int s = t; s < SSP; s += 256) p[s] *= inv;
}

// r[t,g,c] = adj[t,g,:] @ fm[b]^T             per b: [4*cnt,1568]x[834,1568]^T
__global__ void k_r(const float* __restrict__ fm) {
    const int b = blockIdx.z;
    const int off = c_off[b];
    const int cnt = c_off[b + 1] - off;
    gemm_tile_core<true, false, false, false>(
        g_adj + (long)off * NGR * SSP, SSP,
        fm + (long)b * CIN * SSP, SSP,
        g_r + (long)off * NGR * CIN, CIN,
        cnt * NGR, CIN, SSP, nullptr, nullptr, 0);
}

// upd[t,g,f] = r @ W_c[g]^T + b_c[g,f] + emb  per g: [160,834]x[256,834]^T
__global__ void k_upd(const float* __restrict__ Wc, const float* __restrict__ bc) {
    const int g = blockIdx.z;
    gemm_tile_core<true, false, true, true>(
        g_r + g * CIN, NGR * CIN,
        Wc + (long)g * GF * CIN, CIN,
        g_upd + g * GF, NGR * GF,
        TOTAL, GF, CIN,
        bc + g * GF, g_emb + g * GF, NGR * GF);
}

// out[t, g*256+h] = relu(upd @ W_h[g]^T)      per g: [160,256]x[256,256]^T
__global__ void k_head(const float* __restrict__ Wh, float* __restrict__ out) {
    const int g = blockIdx.z;
    gemm_tile_core<true, true, false, false>(
        g_upd + g * GF, NGR * GF,
        Wh + (long)g * GF * GF, GF,
        out + g * GF, NGR * GF,
        TOTAL, GF, GF, nullptr, nullptr, 0);
}

// ---------------------------------------------------------------------------
extern "C" void kernel_launch(void* const* d_in, const int* in_sizes, int n_in,
                              void* d_out, int out_size) {
    const float* actor = (const float*)d_in[0];   // [160,1024]
    const float* fm    = (const float*)d_in[1];   // [16,834,1568]
    const float* Wa    = (const float*)d_in[2];   // [4,256,1024]
    const float* ba    = (const float*)d_in[3];   // [4,256]
    const float* Wc    = (const float*)d_in[4];   // [4,256,834]
    const float* bc    = (const float*)d_in[5];   // [4,256]
    const float* Wh    = (const float*)d_in[6];   // [4,256,256]
    float* out = (float*)d_out;                   // [160, 1024]

    const dim3 blk(256);
    k_emb   <<<dim3(16, 3, 1),  blk>>>(actor, Wa, ba);
    k_q     <<<dim3(14, 3, NGR), blk>>>(Wc);
    k_logits<<<dim3(25, 1, NB), blk>>>(fm);
    k_softmax<<<TOTAL * NGR, 256>>>();
    k_r     <<<dim3(14, 1, NB), blk>>>(fm);
    k_upd   <<<dim3(4, 3, NGR), blk>>>(Wc, bc);
    k_head  <<<dim3(4, 3, NGR), blk>>>(Wh, out);
}

// round 3
// speedup vs baseline: 1.5562x; 1.5562x over previous
#include <cuda_runtime.h>
#include <math.h>

#define TOTAL 160
#define NB    16
#define NGR   4
#define DIM   1024
#define CIN   834
#define GF    256
#define SSP   1568   // 8*14*14

// Ragged bookkeeping (static per problem spec)
__constant__ int c_off[NB + 1] = {0, 6, 20, 30, 38, 54, 66, 75, 86, 93,
                                  106, 116, 126, 134, 146, 152, 160};

// Scratch (device globals — no runtime allocation)
__device__ float g_emb[TOTAL * NGR * GF];    // [t][g*256+f]        ld 1024
__device__ float g_q  [TOTAL * NGR * CIN];   // [t][g*834+c]        rows (t,g) ld 834
__device__ float g_adj[TOTAL * NGR * SSP];   // [(t,g)][s]          ld 1568
__device__ float g_r  [TOTAL * NGR * CIN];   // rows (t,g) ld 834
__device__ float g_upd[TOTAL * NGR * GF];    // [t][g*256+f]        ld 1024

__device__ __forceinline__ float tf32_hi(float v) {
    return __uint_as_float(__float_as_uint(v) & 0xFFFFE000u);
}

__device__ __forceinline__ void mma8(float* d, const float* a, const float* b) {
    unsigned const* A = reinterpret_cast<unsigned const*>(a);
    unsigned const* B = reinterpret_cast<unsigned const*>(b);
    asm volatile(
        "mma.sync.aligned.m16n8k8.row.col.f32.tf32.tf32.f32 "
        "{%0,%1,%2,%3}, {%4,%5,%6,%7}, {%8,%9}, {%0,%1,%2,%3};\n"
        : "+f"(d[0]), "+f"(d[1]), "+f"(d[2]), "+f"(d[3])
        : "r"(A[0]), "r"(A[1]), "r"(A[2]), "r"(A[3]), "r"(B[0]), "r"(B[1]));
}

// ---------------------------------------------------------------------------
// Tensor-core fp32 GEMM via 3xTF32 split. C[M,N] = A[M,K] * op(B) (+epilogue)
// A row-major [M,K]. TB=false: B row-major [K,N]; TB=true: B row-major [N,K].
// VECB: B global loads may use float4 (requires ldb%4==0; N-tail handled by
//       row guard only in TB path, full-width N in !TB path).
// Block: 64x64, K-tile 32, 256 threads = 8 warps (2 M x 4 N), warp tile 32x16.
// ---------------------------------------------------------------------------
template<bool TB, bool VECB, bool RELU, bool BIAS, bool ADDEND>
__device__ __forceinline__ void mma_gemm_core(
    const float* __restrict__ A, int lda,
    const float* __restrict__ B, int ldb,
    float* __restrict__ C, int ldc,
    int M, int N, int K,
    const float* __restrict__ bias,
    const float* __restrict__ add, int ldadd)
{
    constexpr int BM = 64, BN = 64, BK = 32, PAD = 36;
    __shared__ float As[BM][PAD];
    __shared__ float Bs[BN][PAD];

    const int tid  = threadIdx.x;
    const int lane = tid & 31;
    const int wid  = tid >> 5;
    const int wm   = wid & 1;        // 2 warps along M
    const int wn   = wid >> 1;       // 4 warps along N
    const int gq   = lane >> 2;      // groupID 0..7
    const int tq   = lane & 3;       // thread in group 0..3
    const int m0   = blockIdx.y * BM;
    const int n0   = blockIdx.x * BN;

    float acc[2][2][4];
#pragma unroll
    for (int i = 0; i < 2; i++)
#pragma unroll
        for (int j = 0; j < 2; j++)
#pragma unroll
            for (int q = 0; q < 4; q++) acc[i][j][q] = 0.f;

    for (int kt = 0; kt < K; kt += BK) {
        // ---- load A tile (scalar, guarded): rows tid>>2, cols (tid&3)*8..+7
        {
            const int r  = tid >> 2;
            const int c0 = (tid & 3) * 8;
            const bool rok = (m0 + r) < M;
            const float* Ar = A + (long)(m0 + r) * lda + kt;
#pragma unroll
            for (int j = 0; j < 8; j++) {
                const int k = c0 + j;
                As[r][k] = (rok && (kt + k) < K) ? Ar[k] : 0.f;
            }
        }
        // ---- load B tile -> Bs[n][k]
        if (TB) {
            const int r  = tid >> 2;
            const int c0 = (tid & 3) * 8;
            const bool rok = (n0 + r) < N;
            const float* Br = B + (long)(n0 + r) * ldb + kt;
            if (VECB) {
                // K is multiple of 32 in all VECB+TB uses; row guard only
                if (rok) {
                    float4 v0 = *reinterpret_cast<const float4*>(Br + c0);
                    float4 v1 = *reinterpret_cast<const float4*>(Br + c0 + 4);
                    Bs[r][c0+0]=v0.x; Bs[r][c0+1]=v0.y; Bs[r][c0+2]=v0.z; Bs[r][c0+3]=v0.w;
                    Bs[r][c0+4]=v1.x; Bs[r][c0+5]=v1.y; Bs[r][c0+6]=v1.z; Bs[r][c0+7]=v1.w;
                } else {
#pragma unroll
                    for (int j = 0; j < 8; j++) Bs[r][c0 + j] = 0.f;
                }
            } else {
#pragma unroll
                for (int j = 0; j < 8; j++) {
                    const int k = c0 + j;
                    Bs[r][k] = (rok && (kt + k) < K) ? Br[k] : 0.f;
                }
            }
        } else {
            const int k  = tid >> 3;        // 0..31
            const int c0 = (tid & 7) * 8;   // 0..56
            const bool kok = (kt + k) < K;
            const float* Br = B + (long)(kt + k) * ldb + n0;
            if (VECB) {
                // N multiple of 64 in all VECB+!TB uses; k guard only
                if (kok) {
                    float4 v0 = *reinterpret_cast<const float4*>(Br + c0);
                    float4 v1 = *reinterpret_cast<const float4*>(Br + c0 + 4);
                    Bs[c0+0][k]=v0.x; Bs[c0+1][k]=v0.y; Bs[c0+2][k]=v0.z; Bs[c0+3][k]=v0.w;
                    Bs[c0+4][k]=v1.x; Bs[c0+5][k]=v1.y; Bs[c0+6][k]=v1.z; Bs[c0+7][k]=v1.w;
                } else {
#pragma unroll
                    for (int j = 0; j < 8; j++) Bs[c0 + j][k] = 0.f;
                }
            } else {
#pragma unroll
                for (int j = 0; j < 8; j++) {
                    const int n = c0 + j;
                    Bs[n][k] = (kok && (n0 + n) < N) ? Br[n] : 0.f;
                }
            }
        }
        __syncthreads();

#pragma unroll
        for (int kk = 0; kk < BK; kk += 8) {
            float ah[2][4], al[2][4];
#pragma unroll
            for (int mi = 0; mi < 2; mi++) {
                const int rb = wm * 32 + mi * 16;
#pragma unroll
                for (int q = 0; q < 4; q++) {
                    const int rr = rb + gq + (q & 1) * 8;
                    const int cc = kk + tq + (q >> 1) * 4;
                    const float v = As[rr][cc];
                    const float h = tf32_hi(v);
                    ah[mi][q] = h;
                    al[mi][q] = tf32_hi(v - h);
                }
            }
            float bh[2][2], bl[2][2];
#pragma unroll
            for (int ni = 0; ni < 2; ni++) {
                const int nb = wn * 16 + ni * 8 + gq;
#pragma unroll
                for (int q = 0; q < 2; q++) {
                    const float v = Bs[nb][kk + tq + q * 4];
                    const float h = tf32_hi(v);
                    bh[ni][q] = h;
                    bl[ni][q] = tf32_hi(v - h);
                }
            }
#pragma unroll
            for (int mi = 0; mi < 2; mi++)
#pragma unroll
                for (int ni = 0; ni < 2; ni++) {
                    mma8(acc[mi][ni], al[mi], bh[ni]);
                    mma8(acc[mi][ni], ah[mi], bl[ni]);
                    mma8(acc[mi][ni], ah[mi], bh[ni]);
                }
        }
        __syncthreads();
    }

    // ---- epilogue
#pragma unroll
    for (int mi = 0; mi < 2; mi++)
#pragma unroll
        for (int ni = 0; ni < 2; ni++)
#pragma unroll
            for (int q = 0; q < 4; q++) {
                const int m = m0 + wm * 32 + mi * 16 + gq + (q >> 1) * 8;
                const int n = n0 + wn * 16 + ni * 8 + tq * 2 + (q & 1);
                if (m < M && n < N) {
                    float v = acc[mi][ni][q];
                    if (BIAS)   v += bias[n];
                    if (ADDEND) v += add[(long)m * ldadd + n];
                    if (RELU)   v = fmaxf(v, 0.f);
                    C[(long)m * ldc + n] = v;
                }
            }
}

// ---------------------------------------------------------------------------
// Stage kernels
// ---------------------------------------------------------------------------

// emb = actor @ Wa^T + ba     [160,1024] x [1024,1024]^T
__global__ void k_emb(const float* __restrict__ A, const float* __restrict__ Wa,
                      const float* __restrict__ ba) {
    mma_gemm_core<true, true, false, true, false>(
        A, DIM, Wa, DIM, g_emb, NGR * GF,
        TOTAL, NGR * GF, DIM, ba, nullptr, 0);
}

// q[t,g,:] = emb[t,g,:] @ Wc[g]   per g: [160,256] x [256,834]
__global__ void k_q(const float* __restrict__ Wc) {
    const int g = blockIdx.z;
    mma_gemm_core<false, false, false, false, false>(
        g_emb + g * GF, NGR * GF,
        Wc + (long)g * GF * CIN, CIN,
        g_q + g * CIN, NGR * CIN,
        TOTAL, CIN, GF, nullptr, nullptr, 0);
}

// logits rows (t,g) = q @ fm[b]   per b: [cnt*4,834] x [834,1568]
__global__ void k_logits(const float* __restrict__ fm) {
    const int b   = blockIdx.z;
    const int off = c_off[b];
    const int cnt = c_off[b + 1] - off;
    mma_gemm_core<false, true, false, false, false>(
        g_q + (long)off * NGR * CIN, CIN,
        fm + (long)b * CIN * SSP, SSP,
        g_adj + (long)off * NGR * SSP, SSP,
        cnt * NGR, SSP, CIN, nullptr, nullptr, 0);
}

// softmax over s, in place. One block per (t,g) row.
__global__ void k_softmax() {
    const int row = blockIdx.x;
    float* __restrict__ p = g_adj + (long)row * SSP;
    const int t = threadIdx.x;
    __shared__ float sh[8];

    float mx = -1e30f;
    for (int s = t; s < SSP; s += 256) mx = fmaxf(mx, p[s]);
#pragma unroll
    for (int o = 16; o; o >>= 1) mx = fmaxf(mx, __shfl_xor_sync(0xffffffffu, mx, o));
    if ((t & 31) == 0) sh[t >> 5] = mx;
    __syncthreads();
    if (t == 0) {
        float v = sh[0];
        for (int i = 1; i < 8; i++) v = fmaxf(v, sh[i]);
        sh[0] = v;
    }
    __syncthreads();
    mx = sh[0];
    __syncthreads();

    float sum = 0.f;
    for (int s = t; s < SSP; s += 256) {
        const float e = __expf(p[s] - mx);
        p[s] = e;
        sum += e;
    }
#pragma unroll
    for (int o = 16; o; o >>= 1) sum += __shfl_xor_sync(0xffffffffu, sum, o);
    if ((t & 31) == 0) sh[t >> 5] = sum;
    __syncthreads();
    if (t == 0) {
        float v = 0.f;
        for (int i = 0; i < 8; i++) v += sh[i];
        sh[0] = 1.f / v;
    }
    __syncthreads();
    const float inv = sh[0];
    for (int s = t; s < SSP; s += 256) p[s] *= inv;
}

// r rows (t,g) = adj @ fm[b]^T    per b: [cnt*4,1568] x [834,1568]^T
__global__ void k_r(const float* __restrict__ fm) {
    const int b   = blockIdx.z;
    const int off = c_off[b];
    const int cnt = c_off[b + 1] - off;
    mma_gemm_core<true, true, false, false, false>(
        g_adj + (long)off * NGR * SSP, SSP,
        fm + (long)b * CIN * SSP, SSP,
        g_r + (long)off * NGR * CIN, CIN,
        cnt * NGR, CIN, SSP, nullptr, nullptr, 0);
}

// upd[t,g,:] = r @ Wc[g]^T + bc[g] + emb   per g: [160,834] x [256,834]^T
__global__ void k_upd(const float* __restrict__ Wc, const float* __restrict__ bc) {
    const int g = blockIdx.z;
    mma_gemm_core<true, false, false, true, true>(
        g_r + g * CIN, NGR * CIN,
        Wc + (long)g * GF * CIN, CIN,
        g_upd + g * GF, NGR * GF,
        TOTAL, GF, CIN,
        bc + g * GF, g_emb + g * GF, NGR * GF);
}

// out[t, g*256+h] = relu(upd @ Wh[g]^T)    per g: [160,256] x [256,256]^T
__global__ void k_head(const float* __restrict__ Wh, float* __restrict__ out) {
    const int g = blockIdx.z;
    mma_gemm_core<true, true, true, false, false>(
        g_upd + g * GF, NGR * GF,
        Wh + (long)g * GF * GF, GF,
        out + g * GF, NGR * GF,
        TOTAL, GF, GF, nullptr, nullptr, 0);
}

// ---------------------------------------------------------------------------
extern "C" void kernel_launch(void* const* d_in, const int* in_sizes, int n_in,
                              void* d_out, int out_size) {
    const float* actor = (const float*)d_in[0];   // [160,1024]
    const float* fm    = (const float*)d_in[1];   // [16,834,1568]
    const float* Wa    = (const float*)d_in[2];   // [4,256,1024]
    const float* ba    = (const float*)d_in[3];   // [4,256]
    const float* Wc    = (const float*)d_in[4];   // [4,256,834]
    const float* bc    = (const float*)d_in[5];   // [4,256]
    const float* Wh    = (const float*)d_in[6];   // [4,256,256]
    float* out = (float*)d_out;                   // [160,1024]

    const dim3 blk(256);
    k_emb    <<<dim3(16, 3, 1),   blk>>>(actor, Wa, ba);
    k_q      <<<dim3(14, 3, NGR), blk>>>(Wc);
    k_logits <<<dim3(25, 1, NB),  blk>>>(fm);
    k_softmax<<<TOTAL * NGR, 256>>>();
    k_r      <<<dim3(14, 1, NB),  blk>>>(fm);
    k_upd    <<<dim3(4, 3, NGR),  blk>>>(Wc, bc);
    k_head   <<<dim3(4, 3, NGR),  blk>>>(Wh, out);
}